// round 1
// baseline (speedup 1.0000x reference)
#include <cuda_runtime.h>
#include <cuda_bf16.h>
#include <math.h>

// Problem constants
#define NB 8
#define NC 64
#define NN 4000
#define TILE 128
#define KC 32

// Scratch (device globals; no allocations allowed)
__device__ float         g_featn[NB * NN * NC];   // normalized features, [b][n][c]
__device__ int           g_rowid[NB * NN];        // compacted normal-row indices
__device__ unsigned char g_flag[NB * NN];         // 1 = normal, 0 = anomaly
__device__ int           g_cnt[NB];               // n_norm per batch
__device__ double        g_pos[NB];               // sum exp(sim) over pos pairs
__device__ double        g_neg[NB];               // sum neg-term over cross pairs

// ---------------------------------------------------------------------------
// Kernel 1: row-normalize features. Input layout feat[b][c][n] (stride N over c),
// output g_featn[b][n][c] (row-major, c contiguous). One thread per (b,n) row;
// loads are coalesced across threads (consecutive n for fixed c).
// ---------------------------------------------------------------------------
__global__ void normalize_kernel(const float* __restrict__ feat) {
    int row = blockIdx.x * blockDim.x + threadIdx.x;
    if (row >= NB * NN) return;
    int b = row / NN;
    int n = row - b * NN;
    const float* src = feat + (size_t)b * NC * NN + n;
    float v[NC];
    float ss = 0.f;
#pragma unroll
    for (int c = 0; c < NC; c++) {
        float x = src[(size_t)c * NN];
        v[c] = x;
        ss += x * x;
    }
    float nrm = sqrtf(ss);
    float inv = 1.0f / fmaxf(nrm, 1e-12f);
    float* dst = g_featn + (size_t)row * NC;
#pragma unroll
    for (int c = 0; c < NC; c++) dst[c] = v[c] * inv;
}

// ---------------------------------------------------------------------------
// Kernel 2: per-batch deterministic compaction of normal rows + flags + counts.
// Also zeroes the per-batch accumulators. One block per batch.
// ---------------------------------------------------------------------------
__global__ void compact_kernel(const float* __restrict__ prob) {
    int b = blockIdx.x;
    int tid = threadIdx.x;
    __shared__ int warp_tot[8];
    __shared__ int base;
    if (tid == 0) base = 0;
    __syncthreads();

    for (int c0 = 0; c0 < NN; c0 += 256) {
        int idx = c0 + tid;
        bool nrm = false;
        if (idx < NN) {
            nrm = prob[b * NN + idx] < 0.5f;
            g_flag[b * NN + idx] = nrm ? 1 : 0;
        }
        unsigned m = __ballot_sync(0xffffffffu, nrm);
        int lane = tid & 31, wid = tid >> 5;
        int wpos = __popc(m & ((1u << lane) - 1u));
        if (lane == 0) warp_tot[wid] = __popc(m);
        __syncthreads();
        int woff = 0;
        for (int w = 0; w < wid; w++) woff += warp_tot[w];
        int total = 0;
        for (int w = 0; w < 8; w++) total += warp_tot[w];
        if (nrm) g_rowid[b * NN + base + woff + wpos] = idx;
        __syncthreads();
        if (tid == 0) base += total;
        __syncthreads();
    }
    if (tid == 0) {
        g_cnt[b] = base;
        g_pos[b] = 0.0;
        g_neg[b] = 0.0;
    }
}

// ---------------------------------------------------------------------------
// Kernel 3: fused GEMM + masked transcendental epilogue.
// Block = 256 threads (16x16), tile 128x128, per-thread 8x8, K chunked by 32.
// i runs over COMPACTED normal rows (gather via g_rowid); j runs over all rows.
// sim never materialized; per-block sums -> double atomics per batch.
// ---------------------------------------------------------------------------
__global__ __launch_bounds__(256, 2) void gemm_loss_kernel() {
    int b = blockIdx.z;
    int nn = g_cnt[b];
    int i0 = blockIdx.y * TILE;
    if (i0 >= nn) return;                 // early-skip empty i-tiles (~half)
    int j0 = blockIdx.x * TILE;

    __shared__ float As[KC][TILE + 1];    // [k][i], pad -> conflict-free
    __shared__ float Bs[KC][TILE + 1];    // [k][j]
    __shared__ int s_rid[TILE];
    __shared__ unsigned char s_flag[TILE];
    __shared__ float red[256];

    int tid = threadIdx.x;
    int tx = tid & 15, ty = tid >> 4;

    if (tid < TILE) {
        int ii = i0 + tid;
        s_rid[tid] = (ii < nn) ? g_rowid[b * NN + ii] : -1;
        int jj = j0 + tid;
        s_flag[tid] = (jj < NN) ? g_flag[b * NN + jj] : (unsigned char)2;
    }
    __syncthreads();

    float acc[8][8];
#pragma unroll
    for (int r = 0; r < 8; r++)
#pragma unroll
        for (int s = 0; s < 8; s++) acc[r][s] = 0.f;

    const float* fb = g_featn + (size_t)b * NN * NC;

    for (int kc = 0; kc < NC; kc += KC) {
        if (kc) __syncthreads();          // protect smem reuse
        for (int t = tid; t < TILE * KC; t += 256) {
            int li = t >> 5;              // 0..127 (row within tile)
            int k = t & 31;               // 0..31  (k within chunk)
            int ri = s_rid[li];
            As[k][li] = (ri >= 0) ? fb[(size_t)ri * NC + kc + k] : 0.f;
            int jj = j0 + li;
            Bs[k][li] = (jj < NN) ? fb[(size_t)jj * NC + kc + k] : 0.f;
        }
        __syncthreads();
#pragma unroll
        for (int k = 0; k < KC; k++) {
            float a[8], bb[8];
#pragma unroll
            for (int r = 0; r < 8; r++) a[r] = As[k][ty + 16 * r];
#pragma unroll
            for (int s = 0; s < 8; s++) bb[s] = Bs[k][tx + 16 * s];
#pragma unroll
            for (int r = 0; r < 8; r++)
#pragma unroll
                for (int s = 0; s < 8; s++) acc[r][s] += a[r] * bb[s];
        }
    }

    // Epilogue: masked transcendental reduction (TEMPERATURE=0.1 -> *10)
    float pos = 0.f, neg = 0.f;
#pragma unroll
    for (int r = 0; r < 8; r++) {
        int li = ty + 16 * r;
        int ii = i0 + li;
        if (ii >= nn) continue;
        int orig = s_rid[li];
#pragma unroll
        for (int s = 0; s < 8; s++) {
            int lj = tx + 16 * s;
            unsigned char f = s_flag[lj];
            if (f == 2) continue;         // j out of range
            float sim = acc[r][s] * 10.0f;
            if (f) {                      // j normal: positive pair (excl diag)
                if ((j0 + lj) != orig) pos += __expf(sim);
            } else {                      // j anomaly: cross pair
                float e = __expf(sim);
                float u = __fdividef(1.0f, 1.0f + e);  // = 1 - sigmoid(sim)
                neg -= __logf(u + 1e-6f);
            }
        }
    }

    // Block reduction + double atomics (precision + low contention)
    red[tid] = pos;
    __syncthreads();
    for (int sft = 128; sft; sft >>= 1) {
        if (tid < sft) red[tid] += red[tid + sft];
        __syncthreads();
    }
    float bp = red[0];
    __syncthreads();
    red[tid] = neg;
    __syncthreads();
    for (int sft = 128; sft; sft >>= 1) {
        if (tid < sft) red[tid] += red[tid + sft];
        __syncthreads();
    }
    if (tid == 0) {
        atomicAdd(&g_pos[b], (double)bp);
        atomicAdd(&g_neg[b], (double)red[0]);
    }
}

// ---------------------------------------------------------------------------
// Kernel 4: finalize scalar
// ---------------------------------------------------------------------------
__global__ void finalize_kernel(float* __restrict__ out) {
    int tid = threadIdx.x;
    double per = 0.0, vcnt = 0.0;
    if (tid < NB) {
        int nn = g_cnt[tid];
        int na = NN - nn;
        bool valid = (nn >= 10) && (na >= 5);
        double pc = (double)nn * (double)nn - (double)nn;   // pos pair count
        double cc = (double)nn * (double)na;                // cross pair count
        double pm = g_pos[tid] / (pc > 1.0 ? pc : 1.0);
        double pl = -log(pm + 1e-6);
        double nl = g_neg[tid] / (cc > 1.0 ? cc : 1.0);
        if (valid) { per = pl + nl; vcnt = 1.0; }
    }
    for (int o = 16; o; o >>= 1) {
        per += __shfl_down_sync(0xffffffffu, per, o);
        vcnt += __shfl_down_sync(0xffffffffu, vcnt, o);
    }
    if (tid == 0) out[0] = (float)(per / (vcnt > 1.0 ? vcnt : 1.0));
}

extern "C" void kernel_launch(void* const* d_in, const int* in_sizes, int n_in,
                              void* d_out, int out_size) {
    const float* feat = (const float*)d_in[0];   // [8,64,4000,1]
    const float* prob = (const float*)d_in[1];   // [8,1,4000,1]

    normalize_kernel<<<(NB * NN + 255) / 256, 256>>>(feat);
    compact_kernel<<<NB, 256>>>(prob);
    dim3 grid((NN + TILE - 1) / TILE, (NN + TILE - 1) / TILE, NB);  // (jt, it, b)
    gemm_loss_kernel<<<grid, 256>>>();
    finalize_kernel<<<1, 32>>>((float*)d_out);
}

// round 3
// speedup vs baseline: 3.0729x; 3.0729x over previous
#include <cuda_runtime.h>
#include <cuda_bf16.h>
#include <stdint.h>
#include <math.h>

#define NB 8
#define NC 64
#define NN 4000
#define TILE 128
#define SMSTRIDE 72   // 64 bf16 + 8 pad -> 144B row stride, ldmatrix conflict-free

// Scratch (device globals; no allocations allowed)
__device__ __nv_bfloat16 g_featn[NB * NN * NC];  // normalized features bf16, [b][n][c]
__device__ int           g_ridN[NB * NN];        // compacted normal-row indices
__device__ int           g_ridA[NB * NN];        // compacted anomaly-row indices
__device__ int           g_cnt[NB];              // n_norm per batch
__device__ double        g_pos[NB];
__device__ double        g_neg[NB];

// ---------------------------------------------------------------------------
// Kernel 1: row-normalize (fp32 math) -> bf16 output [b][n][c]
// ---------------------------------------------------------------------------
__global__ void normalize_kernel(const float* __restrict__ feat) {
    int row = blockIdx.x * blockDim.x + threadIdx.x;
    if (row >= NB * NN) return;
    int b = row / NN;
    int n = row - b * NN;
    const float* src = feat + (size_t)b * NC * NN + n;
    float v[NC];
    float ss = 0.f;
#pragma unroll
    for (int c = 0; c < NC; c++) {
        float x = src[(size_t)c * NN];
        v[c] = x;
        ss += x * x;
    }
    float inv = 1.0f / fmaxf(sqrtf(ss), 1e-12f);
    __nv_bfloat16* dst = g_featn + (size_t)row * NC;
#pragma unroll
    for (int c = 0; c < NC; c++) dst[c] = __float2bfloat16(v[c] * inv);
}

// ---------------------------------------------------------------------------
// Kernel 2: compact normal AND anomaly index lists per batch (deterministic)
// ---------------------------------------------------------------------------
__global__ void compact_kernel(const float* __restrict__ prob) {
    int b = blockIdx.x;
    int tid = threadIdx.x;
    __shared__ int wtN[8], wtA[8];
    __shared__ int baseN, baseA;
    if (tid == 0) { baseN = 0; baseA = 0; }
    __syncthreads();

    for (int c0 = 0; c0 < NN; c0 += 256) {
        int idx = c0 + tid;
        bool inr = idx < NN;
        bool nrm = false;
        if (inr) nrm = prob[b * NN + idx] < 0.5f;
        bool ano = inr && !nrm;
        unsigned mN = __ballot_sync(0xffffffffu, nrm);
        unsigned mA = __ballot_sync(0xffffffffu, ano);
        int lane = tid & 31, wid = tid >> 5;
        unsigned below = (1u << lane) - 1u;
        int pN = __popc(mN & below), pA = __popc(mA & below);
        if (lane == 0) { wtN[wid] = __popc(mN); wtA[wid] = __popc(mA); }
        __syncthreads();
        int oN = 0, oA = 0, tN = 0, tA = 0;
        for (int w = 0; w < 8; w++) {
            if (w < wid) { oN += wtN[w]; oA += wtA[w]; }
            tN += wtN[w]; tA += wtA[w];
        }
        if (nrm) g_ridN[b * NN + baseN + oN + pN] = idx;
        if (ano) g_ridA[b * NN + baseA + oA + pA] = idx;
        __syncthreads();
        if (tid == 0) { baseN += tN; baseA += tA; }
        __syncthreads();
    }
    if (tid == 0) {
        g_cnt[b] = baseN;
        g_pos[b] = 0.0;
        g_neg[b] = 0.0;
    }
}

// ---------------------------------------------------------------------------
// Tensor-core fused GEMM + loss. MODE 0: pos (normal x normal, skip diag),
// MODE 1: neg (normal x anomaly). mma.sync m16n8k16 bf16 -> fp32.
// Block 256 thr (8 warps, 4x2), tile 128x128, full K=64 resident in smem.
// ---------------------------------------------------------------------------
__device__ __forceinline__ void ldm_x4(unsigned r[4], unsigned addr) {
    asm volatile("ldmatrix.sync.aligned.m8n8.x4.shared.b16 {%0,%1,%2,%3}, [%4];\n"
                 : "=r"(r[0]), "=r"(r[1]), "=r"(r[2]), "=r"(r[3]) : "r"(addr));
}
__device__ __forceinline__ void mma_bf16(float d[4], const unsigned a[4],
                                         const unsigned b2[2]) {
    asm volatile(
        "mma.sync.aligned.m16n8k16.row.col.f32.bf16.bf16.f32 "
        "{%0,%1,%2,%3}, {%4,%5,%6,%7}, {%8,%9}, {%0,%1,%2,%3};\n"
        : "+f"(d[0]), "+f"(d[1]), "+f"(d[2]), "+f"(d[3])
        : "r"(a[0]), "r"(a[1]), "r"(a[2]), "r"(a[3]), "r"(b2[0]), "r"(b2[1]));
}

template <int MODE>
__global__ __launch_bounds__(256, 2) void mma_loss_kernel() {
    int b = blockIdx.z;
    int nI = g_cnt[b];
    int nJ = (MODE == 0) ? nI : (NN - nI);
    int i0 = blockIdx.y * TILE;
    int j0 = blockIdx.x * TILE;
    if (i0 >= nI || j0 >= nJ) return;

    __shared__ __nv_bfloat16 As[TILE][SMSTRIDE];
    __shared__ __nv_bfloat16 Bs[TILE][SMSTRIDE];
    __shared__ float red[256];

    int tid = threadIdx.x;
    const int* ridI = g_ridN + b * NN;
    const int* ridJ = (MODE == 0) ? (g_ridN + b * NN) : (g_ridA + b * NN);
    const __nv_bfloat16* fb = g_featn + (size_t)b * NN * NC;

    // Cooperative tile load: each row = 128B = 8 uint4; zero-pad OOB rows.
    for (int t = tid; t < TILE * 8; t += 256) {
        int r = t >> 3, c = t & 7;
        uint4 v = make_uint4(0, 0, 0, 0);
        int gi = i0 + r;
        if (gi < nI) v = ((const uint4*)(fb + (size_t)ridI[gi] * NC))[c];
        *(uint4*)&As[r][c * 8] = v;
        uint4 w = make_uint4(0, 0, 0, 0);
        int gj = j0 + r;
        if (gj < nJ) w = ((const uint4*)(fb + (size_t)ridJ[gj] * NC))[c];
        *(uint4*)&Bs[r][c * 8] = w;
    }
    __syncthreads();

    int warp = tid >> 5, lane = tid & 31;
    int wm = warp >> 1, wn = warp & 1;      // 4 (M) x 2 (N) warps
    int mBase = wm * 32, nBase = wn * 64;   // warp tile 32 x 64

    float acc[2][8][4];
#pragma unroll
    for (int mi = 0; mi < 2; mi++)
#pragma unroll
        for (int ni = 0; ni < 8; ni++)
#pragma unroll
            for (int e = 0; e < 4; e++) acc[mi][ni][e] = 0.f;

#pragma unroll
    for (int ks = 0; ks < 4; ks++) {
        int k0 = ks * 16;
        unsigned afr[2][4];
#pragma unroll
        for (int mi = 0; mi < 2; mi++) {
            unsigned a = (unsigned)__cvta_generic_to_shared(
                &As[mBase + mi * 16 + (lane & 15)][k0 + (lane >> 4) * 8]);
            ldm_x4(afr[mi], a);
        }
        unsigned bfr[8][2];
#pragma unroll
        for (int np = 0; np < 4; np++) {
            unsigned bt[4];
            unsigned a = (unsigned)__cvta_generic_to_shared(
                &Bs[nBase + np * 16 + (lane & 7) + 8 * (lane >> 4)]
                   [k0 + ((lane >> 3) & 1) * 8]);
            ldm_x4(bt, a);
            bfr[np * 2 + 0][0] = bt[0]; bfr[np * 2 + 0][1] = bt[1];
            bfr[np * 2 + 1][0] = bt[2]; bfr[np * 2 + 1][1] = bt[3];
        }
#pragma unroll
        for (int mi = 0; mi < 2; mi++)
#pragma unroll
            for (int ni = 0; ni < 8; ni++)
                mma_bf16(acc[mi][ni], afr[mi], bfr[ni]);
    }

    // Fused masked transcendental epilogue (TEMPERATURE=0.1 -> *10)
    int g = lane >> 2, tq = lane & 3;
    float sumv = 0.f;
#pragma unroll
    for (int mi = 0; mi < 2; mi++) {
#pragma unroll
        for (int ni = 0; ni < 8; ni++) {
#pragma unroll
            for (int e = 0; e < 4; e++) {
                int ri = i0 + mBase + mi * 16 + g + ((e >> 1) ? 8 : 0);
                int cj = j0 + nBase + ni * 8 + tq * 2 + (e & 1);
                if (ri >= nI || cj >= nJ) continue;
                float sim = acc[mi][ni][e] * 10.0f;
                if (MODE == 0) {
                    if (ri != cj) sumv += __expf(sim);   // diag: same compact idx
                } else {
                    float ex = __expf(sim);
                    float u = __fdividef(1.0f, 1.0f + ex);  // = 1 - sigmoid(sim)
                    sumv -= __logf(u + 1e-6f);
                }
            }
        }
    }

    red[tid] = sumv;
    __syncthreads();
    for (int s = 128; s; s >>= 1) {
        if (tid < s) red[tid] += red[tid + s];
        __syncthreads();
    }
    if (tid == 0) {
        if (MODE == 0) atomicAdd(&g_pos[b], (double)red[0]);
        else           atomicAdd(&g_neg[b], (double)red[0]);
    }
}

// ---------------------------------------------------------------------------
// Finalize scalar
// ---------------------------------------------------------------------------
__global__ void finalize_kernel(float* __restrict__ out) {
    int tid = threadIdx.x;
    double per = 0.0, vcnt = 0.0;
    if (tid < NB) {
        int nn = g_cnt[tid];
        int na = NN - nn;
        bool valid = (nn >= 10) && (na >= 5);
        double pc = (double)nn * (double)nn - (double)nn;
        double cc = (double)nn * (double)na;
        double pm = g_pos[tid] / (pc > 1.0 ? pc : 1.0);
        double pl = -log(pm + 1e-6);
        double nl = g_neg[tid] / (cc > 1.0 ? cc : 1.0);
        if (valid) { per = pl + nl; vcnt = 1.0; }
    }
    for (int o = 16; o; o >>= 1) {
        per += __shfl_down_sync(0xffffffffu, per, o);
        vcnt += __shfl_down_sync(0xffffffffu, vcnt, o);
    }
    if (tid == 0) out[0] = (float)(per / (vcnt > 1.0 ? vcnt : 1.0));
}

extern "C" void kernel_launch(void* const* d_in, const int* in_sizes, int n_in,
                              void* d_out, int out_size) {
    const float* feat = (const float*)d_in[0];   // [8,64,4000,1]
    const float* prob = (const float*)d_in[1];   // [8,1,4000,1]

    normalize_kernel<<<(NB * NN + 255) / 256, 256>>>(feat);
    compact_kernel<<<NB, 256>>>(prob);
    dim3 grid((NN + TILE - 1) / TILE, (NN + TILE - 1) / TILE, NB);  // upper bound; early-exit
    mma_loss_kernel<0><<<grid, 256>>>();
    mma_loss_kernel<1><<<grid, 256>>>();
    finalize_kernel<<<1, 32>>>((float*)d_out);
}